// round 6
// baseline (speedup 1.0000x reference)
#include <cuda_runtime.h>
#include <cuda_bf16.h>
#include <mma.h>
#include <math.h>

using namespace nvcuda;

#define NB      65536
#define DIM     256
#define BANK_N  1000
#define BANK_P  1024

typedef unsigned int       u32;
typedef unsigned long long u64;
typedef __nv_bfloat16      bf16;

// ---------------- device scratch (static) ----------------
__device__ __align__(16) bf16 g_bn0[BANK_P * DIM];
__device__ __align__(16) bf16 g_bn1[BANK_P * DIM];
__device__ __align__(16) bf16 g_bn2[BANK_P * DIM];
__device__ __align__(16) bf16 g_qn0[(size_t)NB * DIM];
__device__ __align__(16) bf16 g_qn1[(size_t)NB * DIM];
__device__ __align__(16) bf16 g_qn2[(size_t)NB * DIM];
__device__ __align__(16) bf16 g_f0[(size_t)NB * DIM];
__device__ __align__(16) bf16 g_f1[(size_t)NB * DIM];
__device__ __align__(16) bf16 g_nf0[(size_t)NB * DIM];
__device__ __align__(16) bf16 g_nf1[(size_t)NB * DIM];
__device__ __align__(16) bf16 g_h0[(size_t)NB * DIM];
__device__ __align__(16) bf16 g_h1[(size_t)NB * DIM];
__device__ __align__(16) bf16 g_w10[DIM * 2 * DIM];
__device__ __align__(16) bf16 g_w11[DIM * 2 * DIM];
__device__ __align__(16) bf16 g_w20[DIM * DIM];
__device__ __align__(16) bf16 g_w21[DIM * DIM];

// ---------------- PTX helpers ----------------
__device__ __forceinline__ u32 smem_u32(const void* p) {
    u32 a;
    asm("{ .reg .u64 t; cvta.to.shared.u64 t, %1; cvt.u32.u64 %0, t; }" : "=r"(a) : "l"(p));
    return a;
}
__device__ __forceinline__ void cp16(u32 dst, const void* src) {
    asm volatile("cp.async.cg.shared.global [%0], [%1], 16;" :: "r"(dst), "l"(src));
}
__device__ __forceinline__ void cp_commit() { asm volatile("cp.async.commit_group;" ::: "memory"); }
__device__ __forceinline__ void cp_wait0()  { asm volatile("cp.async.wait_group 0;" ::: "memory"); }
__device__ __forceinline__ void cp_wait1()  { asm volatile("cp.async.wait_group 1;" ::: "memory"); }

typedef wmma::fragment<wmma::matrix_a, 16, 16, 16, bf16, wmma::row_major> FragA;
typedef wmma::fragment<wmma::matrix_b, 16, 16, 16, bf16, wmma::col_major> FragB;
typedef wmma::fragment<wmma::accumulator, 16, 16, 16, float> FragC;

// ---------------- split kernels (warp per row) ----------------
__device__ __forceinline__ float warp_row_sumsq(float4 v0, float4 v1) {
    float s = v0.x*v0.x + v0.y*v0.y + v0.z*v0.z + v0.w*v0.w
            + v1.x*v1.x + v1.y*v1.y + v1.z*v1.z + v1.w*v1.w;
    #pragma unroll
    for (int o = 16; o; o >>= 1) s += __shfl_xor_sync(0xffffffffu, s, o);
    return s;
}
__device__ __forceinline__ void split2(float x, bf16& a, bf16& b) {
    a = __float2bfloat16(x);
    b = __float2bfloat16(x - __bfloat162float(a));
}
__device__ __forceinline__ void split3(float x, bf16& a, bf16& b, bf16& c) {
    a = __float2bfloat16(x);
    float r = x - __bfloat162float(a);
    b = __float2bfloat16(r);
    c = __float2bfloat16(r - __bfloat162float(b));
}

__global__ void k_bank_split(const float* __restrict__ bank) {
    const int w = threadIdx.x >> 5, l = threadIdx.x & 31;
    const int r = blockIdx.x * 8 + w;
    float4 v0 = make_float4(0,0,0,0), v1 = v0;
    if (r < BANK_N) {
        const float* src = bank + (size_t)r * DIM + l * 8;
        v0 = *(const float4*)src; v1 = *(const float4*)(src + 4);
    }
    const float s = warp_row_sumsq(v0, v1);
    const float inv = 1.0f / fmaxf(sqrtf(s), 1e-12f);
    bf16 o0[8], o1[8], o2[8];
    float xv[8] = {v0.x, v0.y, v0.z, v0.w, v1.x, v1.y, v1.z, v1.w};
    #pragma unroll
    for (int i = 0; i < 8; i++) {
        float q = (r < BANK_N) ? xv[i] * inv : 0.0f;
        split3(q, o0[i], o1[i], o2[i]);
    }
    const size_t o = (size_t)r * DIM + l * 8;
    *(uint4*)(g_bn0 + o) = *(uint4*)o0;
    *(uint4*)(g_bn1 + o) = *(uint4*)o1;
    *(uint4*)(g_bn2 + o) = *(uint4*)o2;
}

__global__ void k_feat_split(const float* __restrict__ feat) {
    const int w = threadIdx.x >> 5, l = threadIdx.x & 31;
    const int r = blockIdx.x * 8 + w;
    const float* src = feat + (size_t)r * DIM + l * 8;
    float4 v0 = *(const float4*)src;
    float4 v1 = *(const float4*)(src + 4);
    const float s = warp_row_sumsq(v0, v1);
    const float inv = 1.0f / fmaxf(sqrtf(s), 1e-12f);
    float xv[8] = {v0.x, v0.y, v0.z, v0.w, v1.x, v1.y, v1.z, v1.w};
    bf16 q0[8], q1[8], q2[8], f0[8], f1[8];
    #pragma unroll
    for (int i = 0; i < 8; i++) {
        split3(xv[i] * inv, q0[i], q1[i], q2[i]);
        split2(xv[i], f0[i], f1[i]);
    }
    const size_t o = (size_t)r * DIM + l * 8;
    *(uint4*)(g_qn0 + o) = *(uint4*)q0;
    *(uint4*)(g_qn1 + o) = *(uint4*)q1;
    *(uint4*)(g_qn2 + o) = *(uint4*)q2;
    *(uint4*)(g_f0 + o)  = *(uint4*)f0;
    *(uint4*)(g_f1 + o)  = *(uint4*)f1;
}

__global__ void k_w_split(const float* __restrict__ W1, const float* __restrict__ W2) {
    const int i = blockIdx.x * 256 + threadIdx.x;
    if (i < DIM * 2 * DIM) split2(W1[i], g_w10[i], g_w11[i]);
    if (i < DIM * DIM)     split2(W2[i], g_w20[i], g_w21[i]);
}

// ---------------- k_sims ----------------
// smem layout (bytes):
//   A resident: 3 splits x 64 x 264 bf16, split stride 33792 B       @0      (101376)
//   B bufs: 2 x [3 splits x (256 x 40 bf16 = 20480 B)], buf 61440 B  @101376 (122880)
//   overlay (valid only between syncs after MMA):
//     Cs 64x264 f32 @101376 ; Vs @168960 ; Is @171520 ; Wt @174080 ; Ix @175360
#define SA_STR   264
#define S_B0     101376
#define S_CS     101376
#define S_VS     168960
#define S_IS     171520
#define S_WT     174080
#define S_IX     175360
#define SIMS_SMEM 224256

__global__ __launch_bounds__(256, 1) void k_sims(const float* __restrict__ bank) {
    extern __shared__ char sm[];
    bf16* As = (bf16*)sm;
    const u32 sb = smem_u32(sm);
    const int t = threadIdx.x, w = t >> 5;
    const int wy = w >> 2, wx = w & 3;
    const int q0 = blockIdx.x * 64;

    const bf16* qnp[3] = {g_qn0, g_qn1, g_qn2};
    const bf16* bnp[3] = {g_bn0, g_bn1, g_bn2};

    // stage B(nt=0,kt=0) into buf0 (async), then A resident (plain stores)
    {
        #pragma unroll
        for (int i = t; i < 3072; i += 256) {
            const int split = i >> 10, rem = i & 1023, col = rem >> 2, seg = rem & 3;
            cp16(sb + S_B0 + split * 20480 + col * 80 + seg * 16,
                 bnp[split] + (size_t)col * DIM + seg * 8);
        }
        cp_commit();
        #pragma unroll
        for (int i = t; i < 6144; i += 256) {
            const int split = i >> 11, rem = i & 2047, row = rem >> 5, seg = rem & 31;
            *(uint4*)(As + split * 16896 + row * SA_STR + seg * 8) =
                *(const uint4*)(qnp[split] + (size_t)(q0 + row) * DIM + seg * 8);
        }
    }

    FragC cbig[2][4], csml[2][4];
    float tv0 = -3e38f, tv1 = -3e38f, tv2 = -3e38f, tv3 = -3e38f, tv4 = -3e38f;
    int   ti0 = 0, ti1 = 0, ti2 = 0, ti3 = 0, ti4 = 0;

    #pragma unroll 1
    for (int nt = 0; nt < 4; nt++) {
        #pragma unroll
        for (int i = 0; i < 2; i++)
            #pragma unroll
            for (int j = 0; j < 4; j++) {
                wmma::fill_fragment(cbig[i][j], 0.0f);
                wmma::fill_fragment(csml[i][j], 0.0f);
            }

        #pragma unroll 1
        for (int kt = 0; kt < 8; kt++) {
            const int buf = kt & 1;
            if (kt < 7) {
                const u32 db = sb + S_B0 + (buf ^ 1) * 61440;
                #pragma unroll
                for (int i = t; i < 3072; i += 256) {
                    const int split = i >> 10, rem = i & 1023, col = rem >> 2, seg = rem & 3;
                    cp16(db + split * 20480 + col * 80 + seg * 16,
                         bnp[split] + (size_t)(nt * 256 + col) * DIM + (kt + 1) * 32 + seg * 8);
                }
                cp_commit();
                cp_wait1();
            } else {
                cp_wait0();
            }
            __syncthreads();

            const bf16* Bb = (bf16*)(sm + S_B0 + buf * 61440);
            #pragma unroll
            for (int kk = 0; kk < 32; kk += 16) {
                FragA a[3][2];
                #pragma unroll
                for (int s = 0; s < 3; s++)
                    #pragma unroll
                    for (int i = 0; i < 2; i++)
                        wmma::load_matrix_sync(a[s][i],
                            As + s * 16896 + (wy * 32 + i * 16) * SA_STR + kt * 32 + kk, SA_STR);
                #pragma unroll
                for (int sb_ = 0; sb_ < 3; sb_++) {
                    FragB b[4];
                    #pragma unroll
                    for (int j = 0; j < 4; j++)
                        wmma::load_matrix_sync(b[j],
                            Bb + sb_ * 10240 + (wx * 64 + j * 16) * 40 + kk, 40);
                    const int npa = (sb_ == 0) ? 3 : (sb_ == 1 ? 2 : 1);
                    #pragma unroll
                    for (int pa = 0; pa < 3; pa++) {
                        if (pa >= npa) break;
                        if (sb_ == 0 && pa == 0) {
                            #pragma unroll
                            for (int i = 0; i < 2; i++)
                                #pragma unroll
                                for (int j = 0; j < 4; j++)
                                    wmma::mma_sync(cbig[i][j], a[0][i], b[j], cbig[i][j]);
                        } else {
                            #pragma unroll
                            for (int i = 0; i < 2; i++)
                                #pragma unroll
                                for (int j = 0; j < 4; j++)
                                    wmma::mma_sync(csml[i][j], a[pa][i], b[j], csml[i][j]);
                        }
                    }
                }
            }
            __syncthreads();
        }

        // merge small into big, spill to Cs overlay (MMA of this chunk done)
        float* Cs = (float*)(sm + S_CS);
        #pragma unroll
        for (int i = 0; i < 2; i++)
            #pragma unroll
            for (int j = 0; j < 4; j++) {
                #pragma unroll
                for (int e = 0; e < cbig[i][j].num_elements; e++)
                    cbig[i][j].x[e] += csml[i][j].x[e];
                wmma::store_matrix_sync(Cs + (wy * 32 + i * 16) * SA_STR + wx * 64 + j * 16,
                                        cbig[i][j], SA_STR, wmma::mem_row_major);
            }
        __syncthreads();

        if (t < 128) {
            const int row = t & 63, half = t >> 6;
            const int base = nt * 256 + half * 128;
            int lim = BANK_N - base; if (lim > 128) lim = 128; if (lim < 0) lim = 0;
            const float* crow = Cs + row * SA_STR + half * 128;
            #pragma unroll 1
            for (int c = 0; c < lim; c++) {
                const float s = crow[c];
                if (s > tv4) {
                    const int idx = base + c;
                    if (s > tv3) {
                        tv4 = tv3; ti4 = ti3;
                        if (s > tv2) {
                            tv3 = tv2; ti3 = ti2;
                            if (s > tv1) {
                                tv2 = tv1; ti2 = ti1;
                                if (s > tv0) { tv1 = tv0; ti1 = ti0; tv0 = s; ti0 = idx; }
                                else         { tv1 = s; ti1 = idx; }
                            } else { tv2 = s; ti2 = idx; }
                        } else { tv3 = s; ti3 = idx; }
                    } else { tv4 = s; ti4 = idx; }
                }
            }
        }
        __syncthreads();

        if (nt < 3) {  // prologue-stage next chunk's kt=0 into buf0
            #pragma unroll
            for (int i = t; i < 3072; i += 256) {
                const int split = i >> 10, rem = i & 1023, col = rem >> 2, seg = rem & 3;
                cp16(sb + S_B0 + split * 20480 + col * 80 + seg * 16,
                     bnp[split] + (size_t)((nt + 1) * 256 + col) * DIM + seg * 8);
            }
            cp_commit();
        }
    }

    // cross-half merge + softmax + gather
    float* Vs = (float*)(sm + S_VS);
    int*   Is = (int*)(sm + S_IS);
    float* Wt = (float*)(sm + S_WT);
    int*   Ix = (int*)(sm + S_IX);
    if (t < 128) {
        Vs[t * 5 + 0] = tv0; Vs[t * 5 + 1] = tv1; Vs[t * 5 + 2] = tv2;
        Vs[t * 5 + 3] = tv3; Vs[t * 5 + 4] = tv4;
        Is[t * 5 + 0] = ti0; Is[t * 5 + 1] = ti1; Is[t * 5 + 2] = ti2;
        Is[t * 5 + 3] = ti3; Is[t * 5 + 4] = ti4;
    }
    __syncthreads();
    if (t < 64) {
        const float* Va = Vs + t * 5;        const int* Ia = Is + t * 5;
        const float* Vb = Vs + (t + 64) * 5; const int* Ib = Is + (t + 64) * 5;
        float mv[5]; int mi[5];
        int ia = 0, ib = 0;
        #pragma unroll
        for (int o = 0; o < 5; o++) {
            const float va = Va[ia], vb = Vb[ib];
            const int xa = Ia[ia], xb = Ib[ib];
            const bool takeA = (va > vb) || (va == vb && xa < xb);
            if (takeA) { mv[o] = va; mi[o] = xa; ia++; }
            else       { mv[o] = vb; mi[o] = xb; ib++; }
        }
        const float m = mv[0];
        float e[5], sum = 0.0f;
        #pragma unroll
        for (int o = 0; o < 5; o++) { e[o] = expf(mv[o] - m); sum += e[o]; }
        const float inv = 1.0f / sum;
        #pragma unroll
        for (int o = 0; o < 5; o++) { Wt[t * 5 + o] = e[o] * inv; Ix[t * 5 + o] = mi[o]; }
    }
    __syncthreads();

    #pragma unroll 1
    for (int r = 0; r < 64; r++) {
        const float w0 = Wt[r * 5 + 0], w1 = Wt[r * 5 + 1], w2 = Wt[r * 5 + 2],
                    w3 = Wt[r * 5 + 3], w4 = Wt[r * 5 + 4];
        const int i0 = Ix[r * 5 + 0], i1 = Ix[r * 5 + 1], i2 = Ix[r * 5 + 2],
                  i3 = Ix[r * 5 + 3], i4 = Ix[r * 5 + 4];
        float v = w0 * __ldg(bank + (size_t)i0 * DIM + t);
        v = fmaf(w1, __ldg(bank + (size_t)i1 * DIM + t), v);
        v = fmaf(w2, __ldg(bank + (size_t)i2 * DIM + t), v);
        v = fmaf(w3, __ldg(bank + (size_t)i3 * DIM + t), v);
        v = fmaf(w4, __ldg(bank + (size_t)i4 * DIM + t), v);
        const size_t o = (size_t)(q0 + r) * DIM + t;
        bf16 n0, n1;
        split2(v, n0, n1);
        g_nf0[o] = n0; g_nf1[o] = n1;
    }
}

// ---------------- MLP kernels ----------------
// per-buf layout (tight): X 2 splits x (64x40 bf16 = 5120 B) @0 ; W 2 splits x
// (256x40 bf16 = 20480 B) @10240 ; buf stride 51200 B, 2 bufs = 102400 B.
// overlay: Cs 64x264 f32 @0.
#define MLP_SMEM 102400

template <int NSLAB, int WLD>
__device__ __forceinline__ void mlp_core(
    const bf16* x0a, const bf16* x1a,   // first-half source splits
    const bf16* x0b, const bf16* x1b,   // second-half source splits
    const bf16* w0p, const bf16* w1p, char* sm, u32 sb, int q0)
{
    const int t = threadIdx.x, w = t >> 5;
    const int wy = w >> 2, wx = w & 3;

    FragC c[2][4];
    #pragma unroll
    for (int i = 0; i < 2; i++)
        #pragma unroll
        for (int j = 0; j < 4; j++) wmma::fill_fragment(c[i][j], 0.0f);

    const bf16* wsp[2] = {w0p, w1p};

    auto stage = [&](int kt, int buf) {
        const u32 bb = sb + buf * 51200;
        const bf16* xpp[2];
        xpp[0] = (kt < NSLAB / 2) ? x0a : x0b;
        xpp[1] = (kt < NSLAB / 2) ? x1a : x1b;
        const int xcol = (kt & 7) * 32;   // DIM/32 - 1 = 7 mask
        #pragma unroll
        for (int i = t; i < 2560; i += 256) {
            if (i < 512) {
                const int split = i >> 8, rem = i & 255, row = rem >> 2, seg = rem & 3;
                cp16(bb + split * 5120 + row * 80 + seg * 16,
                     xpp[split] + (size_t)(q0 + row) * DIM + xcol + seg * 8);
            } else {
                const int j = i - 512;
                const int split = j >> 10, rem = j & 1023, row = rem >> 2, seg = rem & 3;
                cp16(bb + 10240 + split * 20480 + row * 80 + seg * 16,
                     wsp[split] + (size_t)row * WLD + kt * 32 + seg * 8);
            }
        }
        cp_commit();
    };

    stage(0, 0);
    #pragma unroll 1
    for (int kt = 0; kt < NSLAB; kt++) {
        const int buf = kt & 1;
        if (kt < NSLAB - 1) { stage(kt + 1, buf ^ 1); cp_wait1(); }
        else cp_wait0();
        __syncthreads();

        const bf16* Xb = (const bf16*)(sm + buf * 51200);
        const bf16* Wb = (const bf16*)(sm + buf * 51200 + 10240);
        #pragma unroll
        for (int kk = 0; kk < 32; kk += 16) {
            FragA a[2][2];
            #pragma unroll
            for (int s = 0; s < 2; s++)
                #pragma unroll
                for (int i = 0; i < 2; i++)
                    wmma::load_matrix_sync(a[s][i],
                        Xb + s * 2560 + (wy * 32 + i * 16) * 40 + kk, 40);
            #pragma unroll
            for (int sb_ = 0; sb_ < 2; sb_++) {
                FragB b[4];
                #pragma unroll
                for (int j = 0; j < 4; j++)
                    wmma::load_matrix_sync(b[j],
                        Wb + sb_ * 10240 + (wx * 64 + j * 16) * 40 + kk, 40);
                const int npa = (sb_ == 0) ? 2 : 1;
                #pragma unroll
                for (int pa = 0; pa < 2; pa++) {
                    if (pa >= npa) break;
                    #pragma unroll
                    for (int i = 0; i < 2; i++)
                        #pragma unroll
                        for (int j = 0; j < 4; j++)
                            wmma::mma_sync(c[i][j], a[pa][i], b[j], c[i][j]);
                }
            }
        }
        __syncthreads();
    }

    float* Cs = (float*)sm;
    #pragma unroll
    for (int i = 0; i < 2; i++)
        #pragma unroll
        for (int j = 0; j < 4; j++)
            wmma::store_matrix_sync(Cs + (wy * 32 + i * 16) * SA_STR + wx * 64 + j * 16,
                                    c[i][j], SA_STR, wmma::mem_row_major);
    __syncthreads();
}

__global__ __launch_bounds__(256, 1) void k_mlp1(const float* __restrict__ b1) {
    extern __shared__ char sm[];
    const u32 sb = smem_u32(sm);
    const int t = threadIdx.x;
    const int q0 = blockIdx.x * 64;
    mlp_core<16, 2 * DIM>(g_f0, g_f1, g_nf0, g_nf1, g_w10, g_w11, sm, sb, q0);

    const float* Cs = (const float*)sm;
    const float bias = __ldg(b1 + t);
    #pragma unroll 1
    for (int r = 0; r < 64; r++) {
        const float v = fmaxf(Cs[r * SA_STR + t] + bias, 0.0f);
        const size_t o = (size_t)(q0 + r) * DIM + t;
        bf16 h0, h1;
        split2(v, h0, h1);
        g_h0[o] = h0; g_h1[o] = h1;
    }
}

__global__ __launch_bounds__(256, 1) void k_mlp2(const float* __restrict__ b2,
                                                 float* __restrict__ out) {
    extern __shared__ char sm[];
    const u32 sb = smem_u32(sm);
    const int t = threadIdx.x;
    const int q0 = blockIdx.x * 64;
    mlp_core<8, DIM>(g_h0, g_h1, g_h0, g_h1, g_w20, g_w21, sm, sb, q0);

    const float* Cs = (const float*)sm;
    const float bias = __ldg(b2 + t);
    #pragma unroll 1
    for (int r = 0; r < 64; r++)
        out[(size_t)(q0 + r) * DIM + t] = Cs[r * SA_STR + t] + bias;
}

// ---------------------------------------------------------------------------
extern "C" void kernel_launch(void* const* d_in, const int* in_sizes, int n_in,
                              void* d_out, int out_size) {
    const float* feat = (const float*)d_in[0];
    const float* bank = (const float*)d_in[1];
    const float* W1   = (const float*)d_in[2];
    const float* b1   = (const float*)d_in[3];
    const float* W2   = (const float*)d_in[4];
    const float* b2   = (const float*)d_in[5];
    float* out        = (float*)d_out;

    cudaFuncSetAttribute(k_sims, cudaFuncAttributeMaxDynamicSharedMemorySize, SIMS_SMEM);
    cudaFuncSetAttribute(k_mlp1, cudaFuncAttributeMaxDynamicSharedMemorySize, MLP_SMEM);
    cudaFuncSetAttribute(k_mlp2, cudaFuncAttributeMaxDynamicSharedMemorySize, MLP_SMEM);

    k_bank_split<<<BANK_P / 8, 256>>>(bank);
    k_feat_split<<<NB / 8, 256>>>(feat);
    k_w_split<<<(DIM * 2 * DIM + 255) / 256, 256>>>(W1, W2);
    k_sims<<<NB / 64, 256, SIMS_SMEM>>>(bank);
    k_mlp1<<<NB / 64, 256, MLP_SMEM>>>(b1);
    k_mlp2<<<NB / 64, 256, MLP_SMEM>>>(b2, out);
}

// round 8
// speedup vs baseline: 2.4199x; 2.4199x over previous
#include <cuda_runtime.h>
#include <cuda_bf16.h>
#include <mma.h>
#include <math.h>

using namespace nvcuda;

#define NB      65536
#define DIM     256
#define BANK_N  1000
#define BANK_P  1024

typedef unsigned int       u32;
typedef __nv_bfloat16      bf16;

// ---------------- device scratch (static) ----------------
__device__ __align__(16) bf16  g_bn0[BANK_P * DIM];
__device__ __align__(16) bf16  g_qn0[(size_t)NB * DIM];
__device__ __align__(16) float g_binv[BANK_P];
__device__ __align__(16) float g_qinv[NB];
__device__ __align__(16) bf16  g_f0[(size_t)NB * DIM];
__device__ __align__(16) bf16  g_f1[(size_t)NB * DIM];
__device__ __align__(16) bf16  g_nf0[(size_t)NB * DIM];
__device__ __align__(16) bf16  g_nf1[(size_t)NB * DIM];
__device__ __align__(16) bf16  g_h0[(size_t)NB * DIM];
__device__ __align__(16) bf16  g_h1[(size_t)NB * DIM];
__device__ __align__(16) bf16  g_w10[DIM * 2 * DIM];
__device__ __align__(16) bf16  g_w11[DIM * 2 * DIM];
__device__ __align__(16) bf16  g_w20[DIM * DIM];
__device__ __align__(16) bf16  g_w21[DIM * DIM];

// ---------------- helpers ----------------
__device__ __forceinline__ u32 smem_u32(const void* p) {
    u32 a;
    asm("{ .reg .u64 t; cvta.to.shared.u64 t, %1; cvt.u32.u64 %0, t; }" : "=r"(a) : "l"(p));
    return a;
}
__device__ __forceinline__ void cp16(u32 dst, const void* src) {
    asm volatile("cp.async.cg.shared.global [%0], [%1], 16;" :: "r"(dst), "l"(src));
}
__device__ __forceinline__ void cp_commit() { asm volatile("cp.async.commit_group;" ::: "memory"); }
__device__ __forceinline__ void cp_wait0()  { asm volatile("cp.async.wait_group 0;" ::: "memory"); }
__device__ __forceinline__ void cp_wait1()  { asm volatile("cp.async.wait_group 1;" ::: "memory"); }

typedef wmma::fragment<wmma::matrix_a, 16, 16, 16, bf16, wmma::row_major> FragA;
typedef wmma::fragment<wmma::matrix_b, 16, 16, 16, bf16, wmma::col_major> FragB;
typedef wmma::fragment<wmma::accumulator, 16, 16, 16, float> FragC;

__device__ __forceinline__ float warp_row_sumsq(float4 v0, float4 v1) {
    float s = v0.x*v0.x + v0.y*v0.y + v0.z*v0.z + v0.w*v0.w
            + v1.x*v1.x + v1.y*v1.y + v1.z*v1.z + v1.w*v1.w;
    #pragma unroll
    for (int o = 16; o; o >>= 1) s += __shfl_xor_sync(0xffffffffu, s, o);
    return s;
}
__device__ __forceinline__ void split2(float x, bf16& a, bf16& b) {
    a = __float2bfloat16(x);
    b = __float2bfloat16(x - __bfloat162float(a));
}

// ---------------- split kernels ----------------
__global__ void k_bank_split(const float* __restrict__ bank) {
    const int w = threadIdx.x >> 5, l = threadIdx.x & 31;
    const int r = blockIdx.x * 8 + w;
    float4 v0 = make_float4(0,0,0,0), v1 = v0;
    if (r < BANK_N) {
        const float* src = bank + (size_t)r * DIM + l * 8;
        v0 = *(const float4*)src; v1 = *(const float4*)(src + 4);
    }
    const float s = warp_row_sumsq(v0, v1);
    const float inv = 1.0f / fmaxf(sqrtf(s), 1e-12f);
    float xv[8] = {v0.x, v0.y, v0.z, v0.w, v1.x, v1.y, v1.z, v1.w};
    bf16 o0[8];
    #pragma unroll
    for (int i = 0; i < 8; i++)
        o0[i] = __float2bfloat16((r < BANK_N) ? xv[i] * inv : 0.0f);
    *(uint4*)(g_bn0 + (size_t)r * DIM + l * 8) = *(uint4*)o0;
    if (l == 0) g_binv[r] = (r < BANK_N) ? inv : 0.0f;
}

__global__ void k_feat_split(const float* __restrict__ feat) {
    const int w = threadIdx.x >> 5, l = threadIdx.x & 31;
    const int r = blockIdx.x * 8 + w;
    const float* src = feat + (size_t)r * DIM + l * 8;
    float4 v0 = *(const float4*)src;
    float4 v1 = *(const float4*)(src + 4);
    const float s = warp_row_sumsq(v0, v1);
    const float inv = 1.0f / fmaxf(sqrtf(s), 1e-12f);
    float xv[8] = {v0.x, v0.y, v0.z, v0.w, v1.x, v1.y, v1.z, v1.w};
    bf16 q0[8], f0[8], f1[8];
    #pragma unroll
    for (int i = 0; i < 8; i++) {
        q0[i] = __float2bfloat16(xv[i] * inv);
        split2(xv[i], f0[i], f1[i]);
    }
    const size_t o = (size_t)r * DIM + l * 8;
    *(uint4*)(g_qn0 + o) = *(uint4*)q0;
    *(uint4*)(g_f0 + o)  = *(uint4*)f0;
    *(uint4*)(g_f1 + o)  = *(uint4*)f1;
    if (l == 0) g_qinv[r] = inv;
}

__global__ void k_w_split(const float* __restrict__ W1, const float* __restrict__ W2) {
    const int i = blockIdx.x * 256 + threadIdx.x;
    if (i < DIM * 2 * DIM) split2(W1[i], g_w10[i], g_w11[i]);
    if (i < DIM * DIM)     split2(W2[i], g_w20[i], g_w21[i]);
}

// ---------------- k_sims: phase1 bf16 MMA + top12, phase2 fp32 refine ----------------
// smem (bytes):
//  As   @0      64 x 264 bf16                  = 33792   (phase1)
//  Bbuf @33792  2 x (128 x 72 bf16 = 18432)    = 36864   (phase1, per-slab)
//  Cs   @33792  64 x 136 f32 overlay           = 34816   (chunk epilogue)
//  Qf   @0      64 x 264 f32 overlay           = 67584   (phase2)
//  Vs   @70656  128 x 12 f32 ; Is @76800 128x12 i32
//  Ci   @82944  64 x 24 i32 ; Cv @89088 64 x 24 f32 ; Cm @95232 64 i32
//  W5   @95488  64 x 5 f32  ; I5 @96768 64 x 5 i32
#define S_AS 0
#define S_BB 33792
#define S_CS 33792
#define S_QF 0
#define S_VS 70656
#define S_IS 76800
#define S_CI 82944
#define S_CV 89088
#define S_CM 95232
#define S_W5 95488
#define S_I5 96768
#define SIMS_SMEM 98304

__global__ __launch_bounds__(256, 2) void k_sims(const float* __restrict__ feat,
                                                 const float* __restrict__ bank) {
    extern __shared__ char sm[];
    bf16* As = (bf16*)(sm + S_AS);
    const u32 sb = smem_u32(sm);
    const int t = threadIdx.x, w = t >> 5;
    const int wy = w >> 2, wx = w & 3;          // warps 2x4 -> 64 x 128 tile
    const int q0 = blockIdx.x * 64;

    // prologue: async-stage B(nt0,kt0) into buf0, then A resident
    #pragma unroll
    for (int i = t; i < 1024; i += 256) {
        const int c = i >> 3, seg = i & 7;
        cp16(sb + S_BB + c * 144 + seg * 16, g_bn0 + (size_t)c * DIM + seg * 8);
    }
    cp_commit();
    #pragma unroll
    for (int i = t; i < 2048; i += 256) {
        const int row = i >> 5, seg = i & 31;
        *(uint4*)(As + row * 264 + seg * 8) =
            *(const uint4*)(g_qn0 + (size_t)(q0 + row) * DIM + seg * 8);
    }

    // running top-12 (threads 0..127: row = t>>1, half = t&1)
    float tv[12]; int ti[12];
    #pragma unroll
    for (int i = 0; i < 12; i++) { tv[i] = -3e38f; ti[i] = 0; }

    #pragma unroll 1
    for (int nt = 0; nt < 8; nt++) {
        FragC c[2][2];
        #pragma unroll
        for (int i = 0; i < 2; i++)
            #pragma unroll
            for (int j = 0; j < 2; j++) wmma::fill_fragment(c[i][j], 0.0f);

        #pragma unroll 1
        for (int kt = 0; kt < 4; kt++) {
            const int buf = kt & 1;
            if (kt < 3) {
                const u32 db = sb + S_BB + (buf ^ 1) * 18432;
                #pragma unroll
                for (int i = t; i < 1024; i += 256) {
                    const int cc = i >> 3, seg = i & 7;
                    cp16(db + cc * 144 + seg * 16,
                         g_bn0 + (size_t)(nt * 128 + cc) * DIM + (kt + 1) * 64 + seg * 8);
                }
                cp_commit();
                cp_wait1();
            } else {
                cp_wait0();
            }
            __syncthreads();

            const bf16* Bb = (const bf16*)(sm + S_BB + buf * 18432);
            #pragma unroll
            for (int kk = 0; kk < 4; kk++) {
                FragA a[2]; FragB b[2];
                #pragma unroll
                for (int i = 0; i < 2; i++)
                    wmma::load_matrix_sync(a[i],
                        As + (wy * 32 + i * 16) * 264 + kt * 64 + kk * 16, 264);
                #pragma unroll
                for (int j = 0; j < 2; j++)
                    wmma::load_matrix_sync(b[j],
                        Bb + (wx * 32 + j * 16) * 72 + kk * 16, 72);
                #pragma unroll
                for (int i = 0; i < 2; i++)
                    #pragma unroll
                    for (int j = 0; j < 2; j++)
                        wmma::mma_sync(c[i][j], a[i], b[j], c[i][j]);
            }
            __syncthreads();
        }

        // spill sims0 chunk to Cs and scan
        float* Cs = (float*)(sm + S_CS);
        #pragma unroll
        for (int i = 0; i < 2; i++)
            #pragma unroll
            for (int j = 0; j < 2; j++)
                wmma::store_matrix_sync(Cs + (wy * 32 + i * 16) * 136 + wx * 32 + j * 16,
                                        c[i][j], 136, wmma::mem_row_major);
        __syncthreads();

        if (t < 128) {
            const int row = t >> 1, half = t & 1;
            const float* crow = Cs + row * 136 + half * 64;
            const int base = nt * 128 + half * 64;
            #pragma unroll 1
            for (int cc = 0; cc < 64; cc++) {
                const float s = crow[cc];
                const int idx = base + cc;
                if (idx < BANK_N && s > tv[11]) {
                    tv[11] = s; ti[11] = idx;
                    #pragma unroll
                    for (int k = 11; k > 0; k--) {
                        if (tv[k] > tv[k - 1]) {
                            float a = tv[k]; tv[k] = tv[k - 1]; tv[k - 1] = a;
                            int   b = ti[k]; ti[k] = ti[k - 1]; ti[k - 1] = b;
                        }
                    }
                }
            }
        }
        __syncthreads();

        if (nt < 7) {   // stage next chunk's kt0 into buf0 (after scan: Cs overlay done)
            #pragma unroll
            for (int i = t; i < 1024; i += 256) {
                const int cc = i >> 3, seg = i & 7;
                cp16(sb + S_BB + cc * 144 + seg * 16,
                     g_bn0 + (size_t)((nt + 1) * 128 + cc) * DIM + seg * 8);
            }
            cp_commit();
        }
    }

    // dump per-thread lists
    float* Vs = (float*)(sm + S_VS);
    int*   Is = (int*)(sm + S_IS);
    if (t < 128) {
        #pragma unroll
        for (int i = 0; i < 12; i++) { Vs[t * 12 + i] = tv[i]; Is[t * 12 + i] = ti[i]; }
    }
    __syncthreads();

    // merge two half-lists per row, find cutoff, candidate count
    int*   Ci = (int*)(sm + S_CI);
    float* Cv = (float*)(sm + S_CV);
    int*   Cm = (int*)(sm + S_CM);
    if (t < 64) {
        const float* Va = Vs + (2 * t) * 12;       const int* Ia = Is + (2 * t) * 12;
        const float* Vb = Vs + (2 * t + 1) * 12;   const int* Ib = Is + (2 * t + 1) * 12;
        int ia = 0, ib = 0, m = 24;
        float cutoff = -3e38f;
        for (int o = 0; o < 24; o++) {
            const float va = Va[ia], vb = Vb[ib];
            const int xa = Ia[ia], xb = Ib[ib];
            const bool takeA = (va > vb) || (va == vb && xa < xb);
            const float v = takeA ? va : vb;
            const int   x = takeA ? xa : xb;
            if (takeA) { if (ia < 11) ia++; } else { if (ib < 11) ib++; }
            if (o == 4) cutoff = v - 1.5e-3f;
            if (o > 4 && v < cutoff && m == 24) m = o;
            Ci[t * 24 + o] = x;
        }
        Cm[t] = m;
    }
    __syncthreads();

    // phase 2: stage exact qn (fp32) into Qf overlay
    float* Qf = (float*)(sm + S_QF);
    #pragma unroll
    for (int i = t; i < 4096; i += 256) {
        const int row = i >> 6, s4 = i & 63;
        float4 v = *(const float4*)(feat + (size_t)(q0 + row) * DIM + s4 * 4);
        const float inv = g_qinv[q0 + row];
        v.x *= inv; v.y *= inv; v.z *= inv; v.w *= inv;
        *(float4*)(Qf + row * 264 + s4 * 4) = v;
    }
    __syncthreads();

    // exact fp32 dots for candidates (4 threads per row)
    {
        const int row = t & 63, q4 = t >> 6;
        const int m = Cm[row];
        for (int j = q4; j < m; j += 4) {
            const int idx = Ci[row * 24 + j];
            const float4* bp = (const float4*)(bank + (size_t)idx * DIM);
            const float* qp = Qf + row * 264;
            float s0 = 0, s1 = 0, s2 = 0, s3 = 0;
            #pragma unroll 8
            for (int d = 0; d < 64; d++) {
                float4 b4 = __ldg(bp + d);
                float4 qv = *(const float4*)(qp + d * 4);
                s0 = fmaf(qv.x, b4.x, s0);
                s1 = fmaf(qv.y, b4.y, s1);
                s2 = fmaf(qv.z, b4.z, s2);
                s3 = fmaf(qv.w, b4.w, s3);
            }
            Cv[row * 24 + j] = ((s0 + s1) + (s2 + s3)) * g_binv[idx];
        }
    }
    __syncthreads();

    // select exact top-5, softmax
    float* W5 = (float*)(sm + S_W5);
    int*   I5 = (int*)(sm + S_I5);
    if (t < 64) {
        const int m = Cm[t];
        float sv[5]; int si[5];
        #pragma unroll
        for (int k = 0; k < 5; k++) {
            float best = -3e38f; int bidx = 0x7fffffff; int bj = 0;
            for (int j = 0; j < m; j++) {
                const float v = Cv[t * 24 + j];
                const int  id = Ci[t * 24 + j];
                if (v > best || (v == best && id < bidx)) { best = v; bidx = id; bj = j; }
            }
            sv[k] = best; si[k] = bidx;
            Cv[t * 24 + bj] = -3e38f;
        }
        const float mx = sv[0];
        float e[5], sum = 0.0f;
        #pragma unroll
        for (int k = 0; k < 5; k++) { e[k] = expf(sv[k] - mx); sum += e[k]; }
        const float inv = 1.0f / sum;
        #pragma unroll
        for (int k = 0; k < 5; k++) { W5[t * 5 + k] = e[k] * inv; I5[t * 5 + k] = si[k]; }
    }
    __syncthreads();

    // weighted gather (t = dim), bf16 split of nf
    #pragma unroll 1
    for (int r = 0; r < 64; r++) {
        const float w0 = W5[r * 5 + 0], w1 = W5[r * 5 + 1], w2 = W5[r * 5 + 2],
                    w3 = W5[r * 5 + 3], w4 = W5[r * 5 + 4];
        const int i0 = I5[r * 5 + 0], i1 = I5[r * 5 + 1], i2 = I5[r * 5 + 2],
                  i3 = I5[r * 5 + 3], i4 = I5[r * 5 + 4];
        float v = w0 * __ldg(bank + (size_t)i0 * DIM + t);
        v = fmaf(w1, __ldg(bank + (size_t)i1 * DIM + t), v);
        v = fmaf(w2, __ldg(bank + (size_t)i2 * DIM + t), v);
        v = fmaf(w3, __ldg(bank + (size_t)i3 * DIM + t), v);
        v = fmaf(w4, __ldg(bank + (size_t)i4 * DIM + t), v);
        const size_t o = (size_t)(q0 + r) * DIM + t;
        bf16 n0, n1;
        split2(v, n0, n1);
        g_nf0[o] = n0; g_nf1[o] = n1;
    }
}

// ---------------- MLP kernels: 64 rows x 128 out-cols, 32-K slabs, 2 CTAs/SM ----------------
// per buf (30720 B): X 2 splits x (64x40 bf16 = 5120) @0 ; W 2 splits x (128x40 bf16 = 10240) @10240
// 2 bufs = 61440 ; Cs overlay 64x136 f32 = 34816 @0
#define MLP_SMEM 61440

template <int NSLAB, int WLD>
__device__ __forceinline__ void mlp_core(
    const bf16* x0a, const bf16* x1a, const bf16* x0b, const bf16* x1b,
    const bf16* w0p, const bf16* w1p, char* sm, u32 sb, int q0, int o0)
{
    const int t = threadIdx.x, w = t >> 5;
    const int wy = w >> 2, wx = w & 3;

    FragC c[2][2];
    #pragma unroll
    for (int i = 0; i < 2; i++)
        #pragma unroll
        for (int j = 0; j < 2; j++) wmma::fill_fragment(c[i][j], 0.0f);

    const bf16* wsp[2] = {w0p, w1p};

    auto stage = [&](int kt, int buf) {
        const u32 bb = sb + buf * 30720;
        const bf16* xpp[2];
        xpp[0] = (kt < NSLAB / 2) ? x0a : x0b;
        xpp[1] = (kt < NSLAB / 2) ? x1a : x1b;
        const int xcol = (kt & 7) * 32;
        #pragma unroll
        for (int i = t; i < 1536; i += 256) {
            if (i < 512) {
                const int split = i >> 8, rem = i & 255, row = rem >> 2, seg = rem & 3;
                cp16(bb + split * 5120 + row * 80 + seg * 16,
                     xpp[split] + (size_t)(q0 + row) * DIM + xcol + seg * 8);
            } else {
                const int jj = i - 512;
                const int split = jj >> 9, rem = jj & 511, row = rem >> 2, seg = rem & 3;
                cp16(bb + 10240 + split * 10240 + row * 80 + seg * 16,
                     wsp[split] + (size_t)(o0 + row) * WLD + kt * 32 + seg * 8);
            }
        }
        cp_commit();
    };

    stage(0, 0);
    #pragma unroll 1
    for (int kt = 0; kt < NSLAB; kt++) {
        const int buf = kt & 1;
        if (kt < NSLAB - 1) { stage(kt + 1, buf ^ 1); cp_wait1(); }
        else cp_wait0();
        __syncthreads();

        const bf16* Xb = (const bf16*)(sm + buf * 30720);
        const bf16* Wb = (const bf16*)(sm + buf * 30720 + 10240);
        #pragma unroll
        for (int kk = 0; kk < 32; kk += 16) {
            FragA a0[2], a1[2];
            FragB b0[2], b1[2];
            #pragma unroll
            for (int i = 0; i < 2; i++) {
                wmma::load_matrix_sync(a0[i], Xb + (wy * 32 + i * 16) * 40 + kk, 40);
                wmma::load_matrix_sync(a1[i], Xb + 2560 + (wy * 32 + i * 16) * 40 + kk, 40);
            }
            #pragma unroll
            for (int j = 0; j < 2; j++) {
                wmma::load_matrix_sync(b0[j], Wb + (wx * 32 + j * 16) * 40 + kk, 40);
                wmma::load_matrix_sync(b1[j], Wb + 5120 + (wx * 32 + j * 16) * 40 + kk, 40);
            }
            #pragma unroll
            for (int i = 0; i < 2; i++)
                #pragma unroll
                for (int j = 0; j < 2; j++) {
                    wmma::mma_sync(c[i][j], a0[i], b0[j], c[i][j]);
                    wmma::mma_sync(c[i][j], a0[i], b1[j], c[i][j]);
                    wmma::mma_sync(c[i][j], a1[i], b0[j], c[i][j]);
                }
        }
        __syncthreads();
    }

    float* Cs = (float*)sm;
    #pragma unroll
    for (int i = 0; i < 2; i++)
        #pragma unroll
        for (int j = 0; j < 2; j++)
            wmma::store_matrix_sync(Cs + (wy * 32 + i * 16) * 136 + wx * 32 + j * 16,
                                    c[i][j], 136, wmma::mem_row_major);
    __syncthreads();
}

__global__ __launch_bounds__(256, 2) void k_mlp1(const float* __restrict__ b1) {
    extern __shared__ char sm[];
    const u32 sb = smem_u32(sm);
    const int t = threadIdx.x;
    const int q0 = blockIdx.x * 64;
    const int o0 = blockIdx.y * 128;
    mlp_core<16, 2 * DIM>(g_f0, g_f1, g_nf0, g_nf1, g_w10, g_w11, sm, sb, q0, o0);

    const float* Cs = (const float*)sm;
    const int c = t & 127, rr = t >> 7;
    const float bias = __ldg(b1 + o0 + c);
    #pragma unroll 1
    for (int r = rr; r < 64; r += 2) {
        const float v = fmaxf(Cs[r * 136 + c] + bias, 0.0f);
        const size_t o = (size_t)(q0 + r) * DIM + o0 + c;
        bf16 h0, h1;
        split2(v, h0, h1);
        g_h0[o] = h0; g_h1[o] = h1;
    }
}

__global__ __launch_bounds__(256, 2) void k_mlp2(const float* __restrict__ b2,
                                                 float* __restrict__ out) {
    extern __shared__ char sm[];
    const u32 sb = smem_u32(sm);
    const int t = threadIdx.x;
    const int q0 = blockIdx.x * 64;
    const int o0 = blockIdx.y * 128;
    mlp_core<8, DIM>(g_h0, g_h1, g_h0, g_h1, g_w20, g_w21, sm, sb, q0, o0);

    const float* Cs = (const float*)sm;
    const int c = t & 127, rr = t >> 7;
    const float bias = __ldg(b2 + o0 + c);
    #pragma unroll 1
    for (int r = rr; r < 64; r += 2)
        out[(size_t)(q0 + r) * DIM + o0 + c] = Cs[r * 136 + c] + bias;
}

// ---------------------------------------------------------------------------
extern "C" void kernel_launch(void* const* d_in, const int* in_sizes, int n_in,
                              void* d_out, int out_size) {
    const float* feat = (const float*)d_in[0];
    const float* bank = (const float*)d_in[1];
    const float* W1   = (const float*)d_in[2];
    const float* b1   = (const float*)d_in[3];
    const float* W2   = (const float*)d_in[4];
    const float* b2   = (const float*)d_in[5];
    float* out        = (float*)d_out;

    cudaFuncSetAttribute(k_sims, cudaFuncAttributeMaxDynamicSharedMemorySize, SIMS_SMEM);
    cudaFuncSetAttribute(k_mlp1, cudaFuncAttributeMaxDynamicSharedMemorySize, MLP_SMEM);
    cudaFuncSetAttribute(k_mlp2, cudaFuncAttributeMaxDynamicSharedMemorySize, MLP_SMEM);

    k_bank_split<<<BANK_P / 8, 256>>>(bank);
    k_feat_split<<<NB / 8, 256>>>(feat);
    k_w_split<<<(DIM * 2 * DIM + 255) / 256, 256>>>(W1, W2);
    k_sims<<<NB / 64, 256, SIMS_SMEM>>>(feat, bank);
    k_mlp1<<<dim3(NB / 64, 2), 256, MLP_SMEM>>>(b1);
    k_mlp2<<<dim3(NB / 64, 2), 256, MLP_SMEM>>>(b2, out);
}

// round 9
// speedup vs baseline: 2.8421x; 1.1745x over previous
#include <cuda_runtime.h>
#include <cuda_bf16.h>
#include <mma.h>
#include <math.h>

using namespace nvcuda;

#define NB      65536
#define DIM     256
#define BANK_N  1000
#define BANK_P  1024

typedef unsigned int       u32;
typedef __nv_bfloat16      bf16;

// ---------------- device scratch (static) ----------------
__device__ __align__(16) bf16  g_bn0[BANK_P * DIM];
__device__ __align__(16) bf16  g_qn0[(size_t)NB * DIM];
__device__ __align__(16) float g_binv[BANK_P];
__device__ __align__(16) float g_qinv[NB];
__device__ __align__(16) bf16  g_f0[(size_t)NB * DIM];
__device__ __align__(16) bf16  g_f1[(size_t)NB * DIM];
__device__ __align__(16) bf16  g_nf0[(size_t)NB * DIM];
__device__ __align__(16) bf16  g_nf1[(size_t)NB * DIM];
__device__ __align__(16) bf16  g_h0[(size_t)NB * DIM];
__device__ __align__(16) bf16  g_h1[(size_t)NB * DIM];
__device__ __align__(16) bf16  g_w10[DIM * 2 * DIM];
__device__ __align__(16) bf16  g_w11[DIM * 2 * DIM];
__device__ __align__(16) bf16  g_w20[DIM * DIM];
__device__ __align__(16) bf16  g_w21[DIM * DIM];

// ---------------- helpers ----------------
__device__ __forceinline__ u32 smem_u32(const void* p) {
    u32 a;
    asm("{ .reg .u64 t; cvta.to.shared.u64 t, %1; cvt.u32.u64 %0, t; }" : "=r"(a) : "l"(p));
    return a;
}
__device__ __forceinline__ void cp16(u32 dst, const void* src) {
    asm volatile("cp.async.cg.shared.global [%0], [%1], 16;" :: "r"(dst), "l"(src));
}
__device__ __forceinline__ void cp_commit() { asm volatile("cp.async.commit_group;" ::: "memory"); }
__device__ __forceinline__ void cp_wait0()  { asm volatile("cp.async.wait_group 0;" ::: "memory"); }
__device__ __forceinline__ void cp_wait1()  { asm volatile("cp.async.wait_group 1;" ::: "memory"); }

typedef wmma::fragment<wmma::matrix_a, 16, 16, 16, bf16, wmma::row_major> FragA;
typedef wmma::fragment<wmma::matrix_b, 16, 16, 16, bf16, wmma::col_major> FragB;
typedef wmma::fragment<wmma::accumulator, 16, 16, 16, float> FragC;

__device__ __forceinline__ float warp_row_sumsq(float4 v0, float4 v1) {
    float s = v0.x*v0.x + v0.y*v0.y + v0.z*v0.z + v0.w*v0.w
            + v1.x*v1.x + v1.y*v1.y + v1.z*v1.z + v1.w*v1.w;
    #pragma unroll
    for (int o = 16; o; o >>= 1) s += __shfl_xor_sync(0xffffffffu, s, o);
    return s;
}
__device__ __forceinline__ void split2(float x, bf16& a, bf16& b) {
    a = __float2bfloat16(x);
    b = __float2bfloat16(x - __bfloat162float(a));
}

// ---------------- split kernels ----------------
__global__ void k_bank_split(const float* __restrict__ bank) {
    const int w = threadIdx.x >> 5, l = threadIdx.x & 31;
    const int r = blockIdx.x * 8 + w;
    float4 v0 = make_float4(0,0,0,0), v1 = v0;
    if (r < BANK_N) {
        const float* src = bank + (size_t)r * DIM + l * 8;
        v0 = *(const float4*)src; v1 = *(const float4*)(src + 4);
    }
    const float s = warp_row_sumsq(v0, v1);
    const float inv = 1.0f / fmaxf(sqrtf(s), 1e-12f);
    float xv[8] = {v0.x, v0.y, v0.z, v0.w, v1.x, v1.y, v1.z, v1.w};
    bf16 o0[8];
    #pragma unroll
    for (int i = 0; i < 8; i++)
        o0[i] = __float2bfloat16((r < BANK_N) ? xv[i] * inv : 0.0f);
    *(uint4*)(g_bn0 + (size_t)r * DIM + l * 8) = *(uint4*)o0;
    if (l == 0) g_binv[r] = (r < BANK_N) ? inv : 0.0f;
}

__global__ void k_feat_split(const float* __restrict__ feat) {
    const int w = threadIdx.x >> 5, l = threadIdx.x & 31;
    const int r = blockIdx.x * 8 + w;
    const float* src = feat + (size_t)r * DIM + l * 8;
    float4 v0 = *(const float4*)src;
    float4 v1 = *(const float4*)(src + 4);
    const float s = warp_row_sumsq(v0, v1);
    const float inv = 1.0f / fmaxf(sqrtf(s), 1e-12f);
    float xv[8] = {v0.x, v0.y, v0.z, v0.w, v1.x, v1.y, v1.z, v1.w};
    bf16 q0[8], f0[8], f1[8];
    #pragma unroll
    for (int i = 0; i < 8; i++) {
        q0[i] = __float2bfloat16(xv[i] * inv);
        split2(xv[i], f0[i], f1[i]);
    }
    const size_t o = (size_t)r * DIM + l * 8;
    *(uint4*)(g_qn0 + o) = *(uint4*)q0;
    *(uint4*)(g_f0 + o)  = *(uint4*)f0;
    *(uint4*)(g_f1 + o)  = *(uint4*)f1;
    if (l == 0) g_qinv[r] = inv;
}

__global__ void k_w_split(const float* __restrict__ W1, const float* __restrict__ W2) {
    const int i = blockIdx.x * 256 + threadIdx.x;
    if (i < DIM * 2 * DIM) split2(W1[i], g_w10[i], g_w11[i]);
    if (i < DIM * DIM)     split2(W2[i], g_w20[i], g_w21[i]);
}

// ---------------- k_sims ----------------
// smem (bytes):
//  As   @0       64 x 264 bf16                    = 33792  (resident, phase1)
//  Bbuf @33792   2 x (256 x 72 bf16 = 36864)      = 73728  (phase1)  -> end 107520
//  Cs   @33792   64 x 264 f32 overlay             = 67584  (chunk epilogue)
//  Qf   @0       64 x 264 f32 overlay             = 67584  (phase2)
//  Vs   @67584 256x8 f ; Is @75776 256x8 i
//  Ci   @83968 64x32 i ; Cv @92160 64x32 f ; Cm @100352 64 i
//  W5   @100608 64x5 f ; I5 @101888 64x5 i
#define S_AS 0
#define S_BB 33792
#define S_CS 33792
#define S_QF 0
#define S_VS 67584
#define S_IS 75776
#define S_CI 83968
#define S_CV 92160
#define S_CM 100352
#define S_W5 100608
#define S_I5 101888
#define SIMS_SMEM 107520

__global__ __launch_bounds__(256, 2) void k_sims(const float* __restrict__ feat,
                                                 const float* __restrict__ bank) {
    extern __shared__ char sm[];
    bf16* As = (bf16*)(sm + S_AS);
    const u32 sb = smem_u32(sm);
    const int t = threadIdx.x, w = t >> 5;
    const int wy = w >> 2, wx = w & 3;          // 2x4 warps -> CTA tile 64 x 256
    const int q0 = blockIdx.x * 64;

    // prologue: stage B(nt0,kt0) into buf0 (async), then A resident
    #pragma unroll
    for (int i = t; i < 2048; i += 256) {
        const int c = i >> 3, seg = i & 7;
        cp16(sb + S_BB + c * 144 + seg * 16, g_bn0 + (size_t)c * DIM + seg * 8);
    }
    cp_commit();
    #pragma unroll
    for (int i = t; i < 2048; i += 256) {
        const int row = i >> 5, seg = i & 31;
        *(uint4*)(As + row * 264 + seg * 8) =
            *(const uint4*)(g_qn0 + (size_t)(q0 + row) * DIM + seg * 8);
    }

    // running top-8 (all 256 threads: row = t>>2, quarter = t&3)
    float tv[8]; int ti[8];
    #pragma unroll
    for (int i = 0; i < 8; i++) { tv[i] = -3e38f; ti[i] = 0; }

    #pragma unroll 1
    for (int nt = 0; nt < 4; nt++) {
        FragC c[2][4];
        #pragma unroll
        for (int i = 0; i < 2; i++)
            #pragma unroll
            for (int j = 0; j < 4; j++) wmma::fill_fragment(c[i][j], 0.0f);

        #pragma unroll 1
        for (int kt = 0; kt < 4; kt++) {
            const int buf = kt & 1;
            if (kt < 3) {
                const u32 db = sb + S_BB + (buf ^ 1) * 36864;
                #pragma unroll
                for (int i = t; i < 2048; i += 256) {
                    const int cc = i >> 3, seg = i & 7;
                    cp16(db + cc * 144 + seg * 16,
                         g_bn0 + (size_t)(nt * 256 + cc) * DIM + (kt + 1) * 64 + seg * 8);
                }
                cp_commit();
                cp_wait1();
            } else {
                cp_wait0();
            }
            __syncthreads();

            const bf16* Bb = (const bf16*)(sm + S_BB + buf * 36864);
            #pragma unroll
            for (int kk = 0; kk < 4; kk++) {
                FragA a[2];
                #pragma unroll
                for (int i = 0; i < 2; i++)
                    wmma::load_matrix_sync(a[i],
                        As + (wy * 32 + i * 16) * 264 + kt * 64 + kk * 16, 264);
                #pragma unroll
                for (int j = 0; j < 4; j++) {
                    FragB b;
                    wmma::load_matrix_sync(b, Bb + (wx * 64 + j * 16) * 72 + kk * 16, 72);
                    wmma::mma_sync(c[0][j], a[0], b, c[0][j]);
                    wmma::mma_sync(c[1][j], a[1], b, c[1][j]);
                }
            }
            __syncthreads();
        }

        // spill sims0 chunk to Cs overlay and scan
        float* Cs = (float*)(sm + S_CS);
        #pragma unroll
        for (int i = 0; i < 2; i++)
            #pragma unroll
            for (int j = 0; j < 4; j++)
                wmma::store_matrix_sync(Cs + (wy * 32 + i * 16) * 264 + wx * 64 + j * 16,
                                        c[i][j], 264, wmma::mem_row_major);
        __syncthreads();

        {
            const int row = t >> 2, quar = t & 3;
            const float* crow = Cs + row * 264 + quar * 64;
            const int base = nt * 256 + quar * 64;
            #pragma unroll 1
            for (int cc = 0; cc < 64; cc++) {
                const float s = crow[cc];
                const int idx = base + cc;
                if (idx < BANK_N && s > tv[7]) {
                    tv[7] = s; ti[7] = idx;
                    #pragma unroll
                    for (int k = 7; k > 0; k--) {
                        if (tv[k] > tv[k - 1]) {
                            float a = tv[k]; tv[k] = tv[k - 1]; tv[k - 1] = a;
                            int   b = ti[k]; ti[k] = ti[k - 1]; ti[k - 1] = b;
                        }
                    }
                }
            }
        }
        __syncthreads();

        if (nt < 3) {   // stage next chunk's kt0 into buf0 (Cs overlay dead)
            #pragma unroll
            for (int i = t; i < 2048; i += 256) {
                const int cc = i >> 3, seg = i & 7;
                cp16(sb + S_BB + cc * 144 + seg * 16,
                     g_bn0 + (size_t)((nt + 1) * 256 + cc) * DIM + seg * 8);
            }
            cp_commit();
        }
    }

    // dump per-thread top-8 lists
    float* Vs = (float*)(sm + S_VS);
    int*   Is = (int*)(sm + S_IS);
    #pragma unroll
    for (int i = 0; i < 8; i++) { Vs[t * 8 + i] = tv[i]; Is[t * 8 + i] = ti[i]; }
    __syncthreads();

    // merge 4 quarter-lists per row, cutoff, candidate count
    int*   Ci = (int*)(sm + S_CI);
    float* Cv = (float*)(sm + S_CV);
    int*   Cm = (int*)(sm + S_CM);
    if (t < 64) {
        const float* V0 = Vs + (4 * t + 0) * 8; const int* I0 = Is + (4 * t + 0) * 8;
        const float* V1 = Vs + (4 * t + 1) * 8; const int* I1 = Is + (4 * t + 1) * 8;
        const float* V2 = Vs + (4 * t + 2) * 8; const int* I2 = Is + (4 * t + 2) * 8;
        const float* V3 = Vs + (4 * t + 3) * 8; const int* I3 = Is + (4 * t + 3) * 8;
        int p0 = 0, p1 = 0, p2 = 0, p3 = 0, m = 32;
        float cutoff = -3e38f;
        #pragma unroll 1
        for (int o = 0; o < 32; o++) {
            float bv = V0[p0]; int bi = I0[p0]; int bl = 0;
            float v = V1[p1]; int x = I1[p1];
            if (v > bv || (v == bv && x < bi)) { bv = v; bi = x; bl = 1; }
            v = V2[p2]; x = I2[p2];
            if (v > bv || (v == bv && x < bi)) { bv = v; bi = x; bl = 2; }
            v = V3[p3]; x = I3[p3];
            if (v > bv || (v == bv && x < bi)) { bv = v; bi = x; bl = 3; }
            Ci[t * 32 + o] = bi;
            if      (bl == 0) { if (p0 < 7) p0++; }
            else if (bl == 1) { if (p1 < 7) p1++; }
            else if (bl == 2) { if (p2 < 7) p2++; }
            else              { if (p3 < 7) p3++; }
            if (o == 4) cutoff = bv - 1.5e-3f;
            if (o > 4 && bv < cutoff && m == 32) m = o;
        }
        Cm[t] = m;
    }
    __syncthreads();

    // phase 2: stage exact qn (fp32) into Qf overlay
    float* Qf = (float*)(sm + S_QF);
    #pragma unroll
    for (int i = t; i < 4096; i += 256) {
        const int row = i >> 6, s4 = i & 63;
        float4 v = *(const float4*)(feat + (size_t)(q0 + row) * DIM + s4 * 4);
        const float inv = g_qinv[q0 + row];
        v.x *= inv; v.y *= inv; v.z *= inv; v.w *= inv;
        *(float4*)(Qf + row * 264 + s4 * 4) = v;
    }
    __syncthreads();

    // exact fp32 dots for candidates (4 threads per row)
    {
        const int row = t & 63, q4 = t >> 6;
        const int m = Cm[row];
        for (int j = q4; j < m; j += 4) {
            const int idx = Ci[row * 32 + j];
            const float4* bp = (const float4*)(bank + (size_t)idx * DIM);
            const float* qp = Qf + row * 264;
            float s0 = 0, s1 = 0, s2 = 0, s3 = 0;
            #pragma unroll 8
            for (int d = 0; d < 64; d++) {
                float4 b4 = __ldg(bp + d);
                float4 qv = *(const float4*)(qp + d * 4);
                s0 = fmaf(qv.x, b4.x, s0);
                s1 = fmaf(qv.y, b4.y, s1);
                s2 = fmaf(qv.z, b4.z, s2);
                s3 = fmaf(qv.w, b4.w, s3);
            }
            Cv[row * 32 + j] = ((s0 + s1) + (s2 + s3)) * g_binv[idx];
        }
    }
    __syncthreads();

    // exact top-5 + softmax
    float* W5 = (float*)(sm + S_W5);
    int*   I5 = (int*)(sm + S_I5);
    if (t < 64) {
        const int m = Cm[t];
        float sv[5]; int si[5];
        #pragma unroll
        for (int k = 0; k < 5; k++) {
            float best = -3e38f; int bidx = 0x7fffffff; int bj = 0;
            for (int j = 0; j < m; j++) {
                const float v = Cv[t * 32 + j];
                const int  id = Ci[t * 32 + j];
                if (v > best || (v == best && id < bidx)) { best = v; bidx = id; bj = j; }
            }
            sv[k] = best; si[k] = bidx;
            Cv[t * 32 + bj] = -3e38f;
        }
        const float mx = sv[0];
        float e[5], sum = 0.0f;
        #pragma unroll
        for (int k = 0; k < 5; k++) { e[k] = expf(sv[k] - mx); sum += e[k]; }
        const float inv = 1.0f / sum;
        #pragma unroll
        for (int k = 0; k < 5; k++) { W5[t * 5 + k] = e[k] * inv; I5[t * 5 + k] = si[k]; }
    }
    __syncthreads();

    // weighted gather (t = dim), bf16 split of nf
    #pragma unroll 1
    for (int r = 0; r < 64; r++) {
        const float w0 = W5[r * 5 + 0], w1 = W5[r * 5 + 1], w2 = W5[r * 5 + 2],
                    w3 = W5[r * 5 + 3], w4 = W5[r * 5 + 4];
        const int i0 = I5[r * 5 + 0], i1 = I5[r * 5 + 1], i2 = I5[r * 5 + 2],
                  i3 = I5[r * 5 + 3], i4 = I5[r * 5 + 4];
        float v = w0 * __ldg(bank + (size_t)i0 * DIM + t);
        v = fmaf(w1, __ldg(bank + (size_t)i1 * DIM + t), v);
        v = fmaf(w2, __ldg(bank + (size_t)i2 * DIM + t), v);
        v = fmaf(w3, __ldg(bank + (size_t)i3 * DIM + t), v);
        v = fmaf(w4, __ldg(bank + (size_t)i4 * DIM + t), v);
        const size_t o = (size_t)(q0 + r) * DIM + t;
        bf16 n0, n1;
        split2(v, n0, n1);
        g_nf0[o] = n0; g_nf1[o] = n1;
    }
}

// ---------------- MLP kernels: CTA 64 rows x 256 out-cols, warp tile 32x64 ----------------
// per-buf (51200 B): X 2 splits x (64x40 bf16 = 5120) @0 ; W 2 splits x (256x40 bf16 = 20480) @10240
// 2 bufs = 102400 ; Cs overlay 64x264 f32 = 67584 @0
#define MLP_SMEM 102400

template <int NSLAB, int WLD>
__device__ __forceinline__ void mlp_core(
    const bf16* x0a, const bf16* x1a, const bf16* x0b, const bf16* x1b,
    const bf16* w0p, const bf16* w1p, char* sm, u32 sb, int q0)
{
    const int t = threadIdx.x, w = t >> 5;
    const int wy = w >> 2, wx = w & 3;   // 2x4 -> 64 x 256

    FragC c[2][4];
    #pragma unroll
    for (int i = 0; i < 2; i++)
        #pragma unroll
        for (int j = 0; j < 4; j++) wmma::fill_fragment(c[i][j], 0.0f);

    const bf16* wsp[2] = {w0p, w1p};

    auto stage = [&](int kt, int buf) {
        const u32 bb = sb + buf * 51200;
        const bf16* xpp[2];
        xpp[0] = (kt < NSLAB / 2) ? x0a : x0b;
        xpp[1] = (kt < NSLAB / 2) ? x1a : x1b;
        const int xcol = (kt & 7) * 32;
        #pragma unroll
        for (int i = t; i < 2560; i += 256) {
            if (i < 512) {
                const int split = i >> 8, rem = i & 255, row = rem >> 2, seg = rem & 3;
                cp16(bb + split * 5120 + row * 80 + seg * 16,
                     xpp[split] + (size_t)(q0 + row) * DIM + xcol + seg * 8);
            } else {
                const int jj = i - 512;
                const int split = jj >> 10, rem = jj & 1023, row = rem >> 2, seg = rem & 3;
                cp16(bb + 10240 + split * 20480 + row * 80 + seg * 16,
                     wsp[split] + (size_t)row * WLD + kt * 32 + seg * 8);
            }
        }
        cp_commit();
    };

    stage(0, 0);
    #pragma unroll 1
    for (int kt = 0; kt < NSLAB; kt++) {
        const int buf = kt & 1;
        if (kt < NSLAB - 1) { stage(kt + 1, buf ^ 1); cp_wait1(); }
        else cp_wait0();
        __syncthreads();

        const bf16* Xb = (const bf16*)(sm + buf * 51200);
        const bf16* Wb = (const bf16*)(sm + buf * 51200 + 10240);
        #pragma unroll
        for (int kk = 0; kk < 32; kk += 16) {
            FragA a0[2], a1[2];
            #pragma unroll
            for (int i = 0; i < 2; i++) {
                wmma::load_matrix_sync(a0[i], Xb + (wy * 32 + i * 16) * 40 + kk, 40);
                wmma::load_matrix_sync(a1[i], Xb + 2560 + (wy * 32 + i * 16) * 40 + kk, 40);
            }
            #pragma unroll
            for (int sw = 0; sw < 2; sw++) {
                #pragma unroll
                for (int j = 0; j < 4; j++) {
                    FragB b;
                    wmma::load_matrix_sync(b,
                        Wb + sw * 10240 + (wx * 64 + j * 16) * 40 + kk, 40);
                    wmma::mma_sync(c[0][j], a0[0], b, c[0][j]);
                    wmma::mma_sync(c[1][j], a0[1], b, c[1][j]);
                    if (sw == 0) {
                        wmma::mma_sync(c[0][j], a1[0], b, c[0][j]);
                        wmma::mma_sync(c[1][j], a1[1], b, c[1][j]);
                    }
                }
            }
        }
        __syncthreads();
    }

    float* Cs = (float*)sm;
    #pragma unroll
    for (int i = 0; i < 2; i++)
        #pragma unroll
        for (int j = 0; j < 4; j++)
            wmma::store_matrix_sync(Cs + (wy * 32 + i * 16) * 264 + wx * 64 + j * 16,
                                    c[i][j], 264, wmma::mem_row_major);
    __syncthreads();
}

__global__ __launch_bounds__(256, 2) void k_mlp1(const float* __restrict__ b1) {
    extern __shared__ char sm[];
    const u32 sb = smem_u32(sm);
    const int t = threadIdx.x;
    const int q0 = blockIdx.x * 64;
    mlp_core<16, 2 * DIM>(g_f0, g_f1, g_nf0, g_nf1, g_w10, g_w11, sm, sb, q0);

    const float* Cs = (const float*)sm;
    const float bias = __ldg(b1 + t);
    #pragma unroll 1
    for (int r = 0; r < 64; r++) {
        const float v = fmaxf(Cs[r * 264 + t] + bias, 0.0f);
        const size_t o = (size_t)(q0 + r) * DIM + t;
        bf16 h0, h1;
        split2(v, h0, h1);
        g_h0[o] = h0; g_h1[o] = h1;
    }
}

__global__ __launch_bounds__(256, 2) void k_mlp2(const float* __restrict__ b2,
                                                 float* __restrict__ out) {
    extern __shared__ char sm[];
    const u32 sb = smem_u32(sm);
    const int t = threadIdx.x;
    const int q0 = blockIdx.x * 64;
    mlp_core<8, DIM>(g_h0, g_h1, g_h0, g_h1, g_w20, g_w21, sm, sb, q0);

    const float* Cs = (const float*)sm;
    const float bias = __ldg(b2 + t);
    #pragma unroll 1
    for (int r = 0; r < 64; r++)
        out[(size_t)(q0 + r) * DIM + t] = Cs[r * 264 + t] + bias;
}

// ---------------------------------------------------------------------------
extern "C" void kernel_launch(void* const* d_in, const int* in_sizes, int n_in,
                              void* d_out, int out_size) {
    const float* feat = (const float*)d_in[0];
    const float* bank = (const float*)d_in[1];
    const float* W1   = (const float*)d_in[2];
    const float* b1   = (const float*)d_in[3];
    const float* W2   = (const float*)d_in[4];
    const float* b2   = (const float*)d_in[5];
    float* out        = (float*)d_out;

    cudaFuncSetAttribute(k_sims, cudaFuncAttributeMaxDynamicSharedMemorySize, SIMS_SMEM);
    cudaFuncSetAttribute(k_mlp1, cudaFuncAttributeMaxDynamicSharedMemorySize, MLP_SMEM);
    cudaFuncSetAttribute(k_mlp2, cudaFuncAttributeMaxDynamicSharedMemorySize, MLP_SMEM);

    k_bank_split<<<BANK_P / 8, 256>>>(bank);
    k_feat_split<<<NB / 8, 256>>>(feat);
    k_w_split<<<(DIM * 2 * DIM + 255) / 256, 256>>>(W1, W2);
    k_sims<<<NB / 64, 256, SIMS_SMEM>>>(feat, bank);
    k_mlp1<<<NB / 64, 256, MLP_SMEM>>>(b1);
    k_mlp2<<<NB / 64, 256, MLP_SMEM>>>(b2, out);
}